// round 15
// baseline (speedup 1.0000x reference)
#include <cuda_runtime.h>

// RNN: out[n,t,:] = tanh(x[n,t,:]@Wx + b + h_{t-1}@Wh), h_{-1}=h0.
// N=64, T=512, D=256, H=256, all fp32.
//
// SINGLE fused kernel, 64 clusters x 2 CTAs x 256 threads (R14 scan protocol,
// proven). CTA r owns output columns [r*128,+128).
//  Warps 0-3 (A): per step s, dot LOCAL k-half -> p_s (critical), then in the
//    fabric-latency slack: compute xw[s+2] for its own column from SMEM-
//    resident Wx pairs + staged x row -> 4-deep smem ring; stage x row s+3.
//  Warps 4-7 (B): mbar-wait peer h half, dot it, bar2, combine ring-xw + p_s
//    + own part, tanh.approx, write local half, send 4x128B per-warp
//    cp.async.bulk chunks with mbarrier::complete_tx.
// No separate GEMM kernel, no global xw scratch.

#define ULL unsigned long long

static __device__ __forceinline__ ULL pk2(float lo, float hi) {
    ULL r; asm("mov.b64 %0, {%1,%2};" : "=l"(r) : "f"(lo), "f"(hi)); return r;
}
static __device__ __forceinline__ void upk2(ULL v, float& lo, float& hi) {
    asm("mov.b64 {%0,%1}, %2;" : "=f"(lo), "=f"(hi) : "l"(v));
}
static __device__ __forceinline__ ULL f2fma(ULL a, ULL b, ULL c) {
    ULL d; asm("fma.rn.f32x2 %0, %1, %2, %3;" : "=l"(d) : "l"(a), "l"(b), "l"(c)); return d;
}
static __device__ __forceinline__ ULL f2add(ULL a, ULL b) {
    ULL d; asm("add.rn.f32x2 %0, %1, %2;" : "=l"(d) : "l"(a), "l"(b)); return d;
}
static __device__ __forceinline__ unsigned int smem_u32(const void* p) {
    unsigned int a;
    asm("{ .reg .u64 t; cvta.to.shared.u64 t, %1; cvt.u32.u64 %0, t; }"
        : "=r"(a) : "l"(p));
    return a;
}
static __device__ __forceinline__ float fast_tanh(float x) {
    float y;
    asm("tanh.approx.f32 %0, %1;" : "=f"(y) : "f"(x));
    return y;
}
static __device__ __forceinline__ void wait_parity(unsigned int bar, unsigned int par) {
    unsigned int done;
    asm volatile(
        "{ .reg .pred p; "
        "mbarrier.try_wait.parity.acquire.cta.shared::cta.b64 p, [%1], %2; "
        "selp.b32 %0, 1, 0, p; }"
        : "=r"(done) : "r"(bar), "r"(par) : "memory");
    while (!done) {
        asm volatile(
            "{ .reg .pred p; "
            "mbarrier.try_wait.parity.acquire.cta.shared::cta.b64 p, [%1], %2, 0x989680; "
            "selp.b32 %0, 1, 0, p; }"
            : "=r"(done) : "r"(bar), "r"(par) : "memory");
    }
}
// 128-element dot: 32x LDS.128 (broadcast), 64 FFMA2 over 8 chains.
static __device__ __forceinline__ float dot128(const ulonglong2* hp, const ULL* W2) {
    ULL a0 = 0ULL, a1 = 0ULL, a2 = 0ULL, a3 = 0ULL;
    ULL a4 = 0ULL, a5 = 0ULL, a6 = 0ULL, a7 = 0ULL;
#pragma unroll
    for (int q = 0; q < 32; q += 4) {
        ulonglong2 v0 = hp[q],     v1 = hp[q + 1];
        ulonglong2 v2 = hp[q + 2], v3 = hp[q + 3];
        a0 = f2fma(v0.x, W2[2 * q],     a0);
        a1 = f2fma(v0.y, W2[2 * q + 1], a1);
        a2 = f2fma(v1.x, W2[2 * q + 2], a2);
        a3 = f2fma(v1.y, W2[2 * q + 3], a3);
        a4 = f2fma(v2.x, W2[2 * q + 4], a4);
        a5 = f2fma(v2.y, W2[2 * q + 5], a5);
        a6 = f2fma(v3.x, W2[2 * q + 6], a6);
        a7 = f2fma(v3.y, W2[2 * q + 7], a7);
    }
    ULL ss = f2add(f2add(f2add(a0, a1), f2add(a2, a3)),
                   f2add(f2add(a4, a5), f2add(a6, a7)));
    float lo, hi;
    upk2(ss, lo, hi);
    return lo + hi;
}
// xw for ONE column j: 256-k dot of staged x row vs SMEM Wx pair table.
// 64 LDS.128 (x, broadcast) + 128 LDS.64 (Wxs2) + 128 FFMA2 over 4 chains.
static __device__ __forceinline__ float gemm_col(const float* xrow,
                                                 const ULL* Wxs2, int j) {
    const ulonglong2* xp = (const ulonglong2*)xrow;
    ULL a0 = 0ULL, a1 = 0ULL, a2 = 0ULL, a3 = 0ULL;
#pragma unroll
    for (int q = 0; q < 64; q += 2) {
        ulonglong2 xv0 = xp[q];
        ulonglong2 xv1 = xp[q + 1];
        a0 = f2fma(xv0.x, Wxs2[(2 * q)     * 128 + j], a0);
        a1 = f2fma(xv0.y, Wxs2[(2 * q + 1) * 128 + j], a1);
        a2 = f2fma(xv1.x, Wxs2[(2 * q + 2) * 128 + j], a2);
        a3 = f2fma(xv1.y, Wxs2[(2 * q + 3) * 128 + j], a3);
    }
    ULL ss = f2add(f2add(a0, a1), f2add(a2, a3));
    float lo, hi;
    upk2(ss, lo, hi);
    return lo + hi;
}

// ---------------------------------------------------------------------------
// Fused kernel. grid = 128 blocks x 256 thr, cluster (2,1,1).
// ---------------------------------------------------------------------------
__global__ void __launch_bounds__(256, 1) __cluster_dims__(2, 1, 1)
rnn_fused(const float* __restrict__ x, const float* __restrict__ h0g,
          const float* __restrict__ Wx, const float* __restrict__ Wh,
          const float* __restrict__ bias, float* __restrict__ out) {
    extern __shared__ __align__(16) char smraw[];
    ULL*   mbar = (ULL*)smraw;                  // 16 B slot
    float* hloc = (float*)(smraw + 16);         // [2][128]
    float* hrem = hloc + 256;                   // [2][128]
    float* p_s  = hrem + 256;                   // [2][128]
    float* ring = p_s + 256;                    // [4][128] xw values
    float* xs   = ring + 512;                   // [4][256] staged x rows
    ULL*   Wxs2 = (ULL*)(xs + 1024);            // [128 k2][128 j] packed pairs

    const int t     = threadIdx.x;
    const int n     = blockIdx.x >> 1;
    const int r     = blockIdx.x & 1;
    const int jbase = r * 128;
    const int j     = t & 127;
    const int jj    = jbase + j;
    const int g     = t >> 7;              // 0 = group A (local), 1 = group B
    const int kbase = (g == 0) ? jbase : (jbase ^ 128);

    // Register-resident Wh slice: Wh[kbase+k][jj], k-pairs.
    ULL W2[64];
#pragma unroll
    for (int k2 = 0; k2 < 64; k2++) {
        float w0 = Wh[(size_t)(kbase + 2 * k2) * 256 + jj];
        float w1 = Wh[(size_t)(kbase + 2 * k2 + 1) * 256 + jj];
        W2[k2] = pk2(w0, w1);
    }

    // Cooperative Wx pair-table load: Wxs2[k2][j] = {Wx[2k2][jj], Wx[2k2+1][jj]}.
    {
        int k2lo = g * 64;
        for (int k2 = k2lo; k2 < k2lo + 64; k2++) {
            float w0 = Wx[(size_t)(2 * k2) * 256 + jj];
            float w1 = Wx[(size_t)(2 * k2 + 1) * 256 + jj];
            Wxs2[k2 * 128 + j] = pk2(w0, w1);
        }
    }

    if (g == 0) hloc[j] = h0g[(size_t)n * 256 + jbase + j];
    else        hrem[j] = h0g[(size_t)n * 256 + (jbase ^ 128) + j];

    const unsigned int bar_local = smem_u32(mbar);
    if (t == 0) {
        asm volatile("mbarrier.init.shared.b64 [%0], %1;"
                     :: "r"(bar_local), "r"(1) : "memory");
    }
    // Cluster-wide barrier: smem init (incl. Wxs2) visible before traffic.
    asm volatile("barrier.cluster.arrive.aligned;" ::: "memory");
    asm volatile("barrier.cluster.wait.aligned;" ::: "memory");

    const unsigned int peer = r ^ 1;
    unsigned int rem_dst[2], rem_bar;
    {
        unsigned int l0 = smem_u32(&hrem[0]);
        unsigned int l1 = smem_u32(&hrem[128]);
        asm("mapa.shared::cluster.u32 %0, %1, %2;" : "=r"(rem_dst[0]) : "r"(l0), "r"(peer));
        asm("mapa.shared::cluster.u32 %0, %1, %2;" : "=r"(rem_dst[1]) : "r"(l1), "r"(peer));
        asm("mapa.shared::cluster.u32 %0, %1, %2;" : "=r"(rem_bar) : "r"(bar_local), "r"(peer));
    }
    const unsigned int src_loc[2] = { smem_u32(&hloc[0]), smem_u32(&hloc[128]) };

    if (g == 0) {
        // ===== Group A: local-half dotter + xw producer (slack work) =====
        const float* Xg = x + (size_t)n * 512 * 256;
        const float bj  = bias[jj];

        // Prologue: stage x rows 0..2; xw[0], xw[1] into ring.
#pragma unroll
        for (int rr = 0; rr < 3; rr++) {
            float2 v = *(const float2*)(Xg + (size_t)rr * 256 + 2 * j);
            *(float2*)(xs + rr * 256 + 2 * j) = v;
        }
        asm volatile("bar.sync 4, 128;" ::: "memory");
#pragma unroll
        for (int w = 0; w < 2; w++) {
            ring[w * 128 + j] = gemm_col(xs + w * 256, Wxs2, j) + bj;
        }

        for (int s = 0; s < 512; s++) {
            const int cur = s & 1;
            if (s > 0) {
                // Wait for B's hloc[cur] writes from step s-1.
                asm volatile("bar.sync 3, 256;" ::: "memory");
            }
            float part = dot128((const ulonglong2*)&hloc[cur * 128], W2);
            p_s[cur * 128 + j] = part;
            asm volatile("bar.arrive 2, 256;" ::: "memory");

            // ---- slack: produce xw[s+2]; stage x row s+3 ----
            const int s2 = s + 2, s3 = s + 3;
            float2 xnew;
            if (s3 < 512)
                xnew = *(const float2*)(Xg + (size_t)s3 * 256 + 2 * j);  // LDG early
            if (s2 < 512)
                ring[(s2 & 3) * 128 + j] = gemm_col(xs + (s2 & 3) * 256, Wxs2, j) + bj;
            if (s3 < 512)
                *(float2*)(xs + (s3 & 3) * 256 + 2 * j) = xnew;
            // Visibility: ring write (s) -> B's bar.sync2 at s+2 path; xs
            // write (s) -> A's own bar.sync3 at s+1. Both ordered.
        }
    } else {
        // ===== Group B: remote-half dotter + combiner + sender =====
        const int wchunk = (t - 128) >> 5;          // B warp index 0..3
        const unsigned int coff = wchunk * 128;     // 32 floats per warp chunk
        for (int s = 0; s < 512; s++) {
            const int cur = s & 1;
            const int nxt = cur ^ 1;

            // Wait for the peer's half of h[cur] (step s-1's send).
            if (s > 0) wait_parity(bar_local, (unsigned)((s & 1) ^ 1));

            float part = dot128((const ulonglong2*)&hrem[cur * 128], W2);

            // A's dot + ring xw ran in parallel with the fabric window.
            asm volatile("bar.sync 2, 256;" ::: "memory");
            float hn = fast_tanh(ring[(s & 3) * 128 + j] + p_s[cur * 128 + j] + part);
            hloc[nxt * 128 + j] = hn;

            if (s < 511) {
                // Release A for step s+1 (non-blocking).
                asm volatile("bar.arrive 3, 256;" ::: "memory");
                // Per-warp chunked send: this warp's 32 floats are written.
                __syncwarp();
                asm volatile("fence.proxy.async.shared::cta;" ::: "memory");
                if ((t & 31) == 0) {
                    if (wchunk == 0) {
                        // Arm our own barrier for the peer's incoming 512B.
                        asm volatile("mbarrier.arrive.expect_tx.shared::cta.b64 _, [%0], %1;"
                                     :: "r"(bar_local), "r"(512) : "memory");
                    }
                    asm volatile(
                        "cp.async.bulk.shared::cluster.shared::cta.mbarrier::complete_tx::bytes "
                        "[%0], [%1], %2, [%3];"
                        :: "r"(rem_dst[nxt] + coff), "r"(src_loc[nxt] + coff),
                           "r"(128), "r"(rem_bar)
                        : "memory");
                }
            }
            out[((size_t)n * 512 + s) * 256 + jbase + j] = hn;
        }
    }

    // Don't exit while the peer may still write into our SMEM.
    asm volatile("barrier.cluster.arrive.aligned;" ::: "memory");
    asm volatile("barrier.cluster.wait.aligned;" ::: "memory");
}

// ---------------------------------------------------------------------------
extern "C" void kernel_launch(void* const* d_in, const int* in_sizes, int n_in,
                              void* d_out, int out_size) {
    const float* x  = (const float*)d_in[0];  // (64,512,256)
    const float* h0 = (const float*)d_in[1];  // (64,256)
    const float* Wx = (const float*)d_in[2];  // (256,256)
    const float* Wh = (const float*)d_in[3];  // (256,256)
    const float* b  = (const float*)d_in[4];  // (256,)
    float* out = (float*)d_out;               // (64,512,256)

    // smem: 16 + (2*128 + 2*128 + 2*128 + 4*128 + 4*256)*4 + 128*128*8
    //     = 16 + 9216 + 131072 = 140304 B
    const int smem_bytes = 16 + 9216 + 131072;
    static int configured = 0;
    if (!configured) {
        cudaFuncSetAttribute(rnn_fused,
                             cudaFuncAttributeMaxDynamicSharedMemorySize,
                             smem_bytes);
        configured = 1;
    }
    rnn_fused<<<128, 256, smem_bytes>>>(x, h0, Wx, Wh, b, out);
    (void)in_sizes; (void)n_in; (void)out_size;
}